// round 13
// baseline (speedup 1.0000x reference)
#include <cuda_runtime.h>
#include <cstdint>

#define B_SZ  8
#define SEQ   4096
#define HID   1024
#define HID2  (HID / 2)
#define HID4  (HID / 4)
#define DMAX  24             // FIR truncation: g[d] ~ 0.64*0.16^d -> 6e-20 at d=24
#define CHUNKS 16            // time-chunks; block = (b, chunk) covers full h-row
#define CGRP   8             // stored 32-step groups per chunk
#define WGRP   6             // warmup groups (192 steps): 0.9^192 ~ 1.7e-9

// ---------------- LIF step: float-mask form (masks exactly 0.0/1.0) --------------
// w09 = rn(0.9 * v_pre-reset), ns = 1-spike_prev, act = (r<=0), r exact int.
// Every FFMA multiplies by exact 0/1 so rounding == reference's mul+add.
struct SnnState { float w09, ns, act, r; };

__device__ __forceinline__ void snn_step(SnnState& st, float xk,
                                         float& macc, float mc)
{
    float v1 = __fmaf_rn(st.w09, st.ns, xk);          // rn(0.9*v_post + x)
    float ge; asm("set.ge.f32.f32 %0, %1, %2;" : "=f"(ge) : "f"(v1), "f"(1.0f));
    float s  = __fmul_rn(ge, st.act);                 // spike as 0.0/1.0
    st.w09   = __fmul_rn(v1, 0.9f);
    st.ns    = __fmaf_rn(-ge, st.act, 1.0f);          // 1 - spike (exact)
    float rd = fmaxf(__fadd_rn(st.r, -1.0f), 0.0f);   // max(r-1,0), exact
    st.r     = __fmaf_rn(s, 5.0f, rd);                // spike => rd==0 => 5
    asm("set.le.f32.f32 %0, %1, %2;" : "=f"(st.act) : "f"(st.r), "f"(0.0f));
    macc     = __fmaf_rn(s, mc, macc);                // exact bit accumulation
}

// ---------------- single fused kernel: g + scan + u + y(FIR) + write -------------
// 128 blocks of 512 threads: block = (b, chunk) owns the FULL 1024-h row for its
// 256-step stored range (+192-step warmup). Warps 0-1 compute the SSM impulse
// response g[d]=C A^d B on the side (named barrier 1, NO block barriers) while
// warps 2-15 scan immediately; the first epilogue __syncthreads absorbs g.
// Per 32-step group: scan (regs) -> masks to double-buffered smem -> popcount-
// transpose u -> 24-tap FIR y -> write out = spike + y. No global scratch.
__global__ void __launch_bounds__(512) fused_kernel(const float* __restrict__ x,
                                                    const float* __restrict__ Ap,
                                                    const float* __restrict__ Bp,
                                                    const float* __restrict__ Cp,
                                                    const float* __restrict__ Dp,
                                                    float* __restrict__ out)
{
    __shared__ float As[64 * 65];        // A, padded rows (warps 0-1 only)
    __shared__ float Wall[DMAX][65];     // Krylov vectors A^d B, padded
    __shared__ float wping[2][64];
    __shared__ float cs[64];
    __shared__ float g_s[DMAX];
    __shared__ unsigned wsm[2][HID];     // double-buffered group masks
    __shared__ int   part[16 * 32];      // per-warp partial popcounts
    __shared__ float u_s[64];            // [0..31]=prev group u, [32..63]=cur
    __shared__ float y_s[32], y1_s[32];

    const int blk  = blockIdx.x;         // 0..127
    const int c    = blk & (CHUNKS - 1);
    const int b    = blk >> 4;
    const int tid  = threadIdx.x;        // 0..511
    const int wid  = tid >> 5, lane = tid & 31;
    const int h    = tid * 2;            // 2 lanes per thread

    const int warm    = c ? WGRP : 0;
    const int g0      = c * CGRP;
    const int tbegin  = (g0 - warm) * 32;
    const int ngroups = warm + CGRP;     // 8 or 14

    const float2* xp = (const float2*)(x + ((size_t)b * SEQ + tbegin) * HID) + tid;
    float4* out4 = (float4*)(out + ((size_t)b * SEQ + g0 * 32) * HID);

    if (tid < 32) u_s[tid] = 0.0f;       // halo for chunk 0 (own-warp use later)
    const float Ds = __ldg(Dp);

    // issue the x prefetch FIRST so DRAM ramps immediately.
    float2 buf[32];
    #pragma unroll
    for (int i = 0; i < 32; i++) buf[i] = xp[(size_t)i * HID2];
    const float2* xld = xp + (size_t)32 * HID2;

    // ---- g on warps 0-1 ONLY: W_0 = B; W_d = A W_{d-1}; g[d] = C . W_d ----------
    if (wid < 2) {
        for (int i = tid; i < 64 * 64; i += 64)
            As[(i >> 6) * 65 + (i & 63)] = Ap[i];
        cs[tid] = Cp[tid];
        float b0 = Bp[tid];
        wping[0][tid] = b0;
        Wall[0][tid]  = b0;
        asm volatile("bar.sync 1, 64;" ::: "memory");
        const int row = tid;                       // one row per thread
        for (int d = 1; d < DMAX; d++) {
            const float* wprev = wping[(d - 1) & 1];
            float a0 = 0.f, a1 = 0.f, a2 = 0.f, a3 = 0.f;
            #pragma unroll
            for (int s = 0; s < 64; s += 4) {
                a0 += As[row * 65 + s + 0] * wprev[s + 0];
                a1 += As[row * 65 + s + 1] * wprev[s + 1];
                a2 += As[row * 65 + s + 2] * wprev[s + 2];
                a3 += As[row * 65 + s + 3] * wprev[s + 3];
            }
            float wn = (a0 + a1) + (a2 + a3);
            wping[d & 1][row] = wn;
            Wall[d][row] = wn;
            asm volatile("bar.sync 1, 64;" ::: "memory");
        }
        if (tid < DMAX) {                          // 24 final dots, 1 per thread
            float p = 0.f;
            #pragma unroll
            for (int j = 0; j < 64; j++) p += cs[j] * Wall[tid][j];
            g_s[tid] = p;                          // consumed by warp 0 (FIR)
        }
    }

    // ---- scan + per-group epilogue ----------------------------------------------
    SnnState s0 = {0,1,1,0}, s1 = {0,1,1,0};

    for (int gg = 0; gg < ngroups; gg++) {
        const bool pf = (gg + 1 < ngroups);
        float m0l = 0, m0h = 0, m1l = 0, m1h = 0;

        #pragma unroll
        for (int i = 0; i < 32; i++) {
            float2 xk = buf[i];
            if (pf) buf[i] = xld[(size_t)i * HID2];    // prefetch next group
            const float mc = (float)(1u << (i & 15));
            if (i < 16) { snn_step(s0, xk.x, m0l, mc); snn_step(s1, xk.y, m1l, mc); }
            else        { snn_step(s0, xk.x, m0h, mc); snn_step(s1, xk.y, m1h, mc); }
        }
        xld += (size_t)32 * HID2;

        if (gg < warm - 1) continue;     // pure warmup group (uniform branch)

        unsigned* wcur = wsm[gg & 1];    // double buffer: no pre-write barrier
        uint2 mv;
        mv.x = __float2uint_rn(m0l) | (__float2uint_rn(m0h) << 16);
        mv.y = __float2uint_rn(m1l) | (__float2uint_rn(m1h) << 16);
        *(uint2*)&wcur[h] = mv;
        __syncthreads();                               // wsm ready (g also done)

        // u[cur]: popcount transpose (16 warps x 64 words each)
        int cnt = 0;
        #pragma unroll 16
        for (int i2 = 0; i2 < 64; i2++)
            cnt += (int)((wcur[wid * 64 + i2] >> lane) & 1u);
        part[wid * 32 + lane] = cnt;
        __syncthreads();
        if (tid < 32) {
            int tot = 0;
            #pragma unroll
            for (int w2 = 0; w2 < 16; w2++) tot += part[w2 * 32 + tid];
            float uv = (float)tot * (1.0f / (float)HID);
            u_s[32 + tid] = uv;
            float acc = Ds * uv;                       // y = D*u + g (*) u
            #pragma unroll
            for (int d = 0; d < DMAX; d++)
                acc += g_s[d] * u_s[32 + tid - d];
            y_s[tid]  = acc;
            y1_s[tid] = acc + 1.0f;
        }
        __syncthreads();

        if (gg >= warm) {
            // write 32 t x 1024 h: thread = (quad q, t-half hf); STG.128, 512B/warp
            const int q  = tid & 255;
            const int hf = tid >> 8;
            const uint4 w4 = ((const uint4*)wcur)[q];
            float4* rowb = out4 + (size_t)(gg - warm) * 32 * HID4 + q;
            #pragma unroll
            for (int k = 0; k < 16; k++) {
                const int t = hf * 16 + k;
                const float y = y_s[t], y1 = y1_s[t];
                float4 o;
                o.x = ((w4.x >> t) & 1u) ? y1 : y;
                o.y = ((w4.y >> t) & 1u) ? y1 : y;
                o.z = ((w4.z >> t) & 1u) ? y1 : y;
                o.w = ((w4.w >> t) & 1u) ? y1 : y;
                __stcs(&rowb[(size_t)t * HID4], o);
            }
        }
        if (tid < 32) u_s[tid] = u_s[32 + tid];        // slide cur -> prev (warp 0)
    }
}

// ---------------- launch ----------------------------------------------------------
extern "C" void kernel_launch(void* const* d_in, const int* in_sizes, int n_in,
                              void* d_out, int out_size)
{
    const float* x  = (const float*)d_in[0];   // (8, 4096, 1024) f32
    const float* A  = (const float*)d_in[1];   // (64, 64)
    const float* Bv = (const float*)d_in[2];   // (64, 1)
    const float* Cv = (const float*)d_in[3];   // (1, 64)
    const float* Dp = (const float*)d_in[4];   // (1, 1)

    fused_kernel<<<B_SZ * CHUNKS, 512>>>(x, A, Bv, Cv, Dp, (float*)d_out);
}